// round 7
// baseline (speedup 1.0000x reference)
#include <cuda_runtime.h>
#include <math.h>
#include <stdint.h>

#define BB 2
#define TT 2048
#define CC 512
#define NB 4
#define QN (NB*CC)   // 2048
#define HALF (CC/2)  // 256

typedef unsigned long long ull;

// Scratch (no cudaMalloc allowed)
__device__ float g_Q[BB*TT*QN];
__device__ float g_K[BB*TT*CC];
__device__ float g_V[BB*TT*QN];
__device__ float g_Y[BB*TT*CC];

__device__ __forceinline__ uint32_t f2tf32(float f) {
    uint32_t r;
    asm("cvt.rna.tf32.f32 %0, %1;" : "=r"(r) : "f"(f));
    return r;
}
__device__ __forceinline__ void mma_tf32(
    float& c0, float& c1, float& c2, float& c3,
    uint32_t a0, uint32_t a1, uint32_t a2, uint32_t a3,
    uint32_t b0, uint32_t b1)
{
    asm("mma.sync.aligned.m16n8k8.row.col.f32.tf32.tf32.f32 "
        "{%0,%1,%2,%3}, {%4,%5,%6,%7}, {%8,%9}, {%0,%1,%2,%3};"
        : "+f"(c0), "+f"(c1), "+f"(c2), "+f"(c3)
        : "r"(a0), "r"(a1), "r"(a2), "r"(a3), "r"(b0), "r"(b1));
}
// ---- packed f32x2 helpers ----
__device__ __forceinline__ void ffma2(ull &d, ull a, ull b) {
    asm("fma.rn.f32x2 %0, %1, %2, %0;" : "+l"(d) : "l"(a), "l"(b));
}
__device__ __forceinline__ ull fmul2(ull a, ull b) {
    ull r; asm("mul.rn.f32x2 %0, %1, %2;" : "=l"(r) : "l"(a), "l"(b)); return r;
}
__device__ __forceinline__ ull pack2(float x, float y) {
    ull r; asm("mov.b64 %0, {%1, %2};" : "=l"(r) : "f"(x), "f"(y)); return r;
}
__device__ __forceinline__ float2 unpk(ull v) {
    float2 r; asm("mov.b64 {%0, %1}, %2;" : "=f"(r.x), "=f"(r.y) : "l"(v)); return r;
}

// ---------------------------------------------------------------------------
// Tensor-core GEMM (tf32 mma.sync), double-buffered software pipeline.
// Out[M,N] = A[M,K] @ W[K,N], fp32 I/O. SPLIT=1: 3-MMA split-tf32 (~fp32 acc).
// CTA 128x128, BK=16, 8 warps (2Mx4N), warp tile 64x32.
// Dynamic smem: 2 stages of [Ah|Wh|(Al|Wl)] ; pair-swizzled k/4 slot.
// ---------------------------------------------------------------------------
template<int DO_ROPE, int SPLIT>
__global__ void __launch_bounds__(256) gemm_tc(
    const float* __restrict__ A, const float* __restrict__ W, float* __restrict__ Out,
    int M, int N, int K,
    const float* __restrict__ cosT, const float* __restrict__ sinT, float scale)
{
    constexpr int BM = 128, BN = 128, BK = 16;
    constexpr int STAGE = SPLIT ? 8192 : 4096;   // u32 per stage
    extern __shared__ uint32_t sm[];

    const int tid    = threadIdx.x;
    const int warpid = tid >> 5;
    const int lane   = tid & 31;
    const int g      = lane >> 2;
    const int tig    = lane & 3;
    const int wm = (warpid & 1) * 64;
    const int wn = (warpid >> 1) * 32;
    const int rowBase = blockIdx.y * BM;
    const int colBase = blockIdx.x * BN;

    // per-thread load coordinates (2 float4 each for A and W)
    const int a_r0  = tid >> 2;        // 0..63 ; second row = +64
    const int a_ix0 = tid & 3;         // k/4 slot
    const int w_kr0 = tid >> 5;        // 0..7 ; second kr = +8
    const int w_nc0 = tid & 31;        // n/4 slot

    float acc[4][4][4];
#pragma unroll
    for (int mt = 0; mt < 4; mt++)
#pragma unroll
        for (int nt = 0; nt < 4; nt++)
#pragma unroll
            for (int c = 0; c < 4; c++) acc[mt][nt][c] = 0.f;

    float4 ra0, ra1, rw0, rw1;

    auto ldg = [&](int k0) {
        ra0 = *(const float4*)(A + (size_t)(rowBase + a_r0)      * K + k0 + a_ix0 * 4);
        ra1 = *(const float4*)(A + (size_t)(rowBase + a_r0 + 64) * K + k0 + a_ix0 * 4);
        rw0 = *(const float4*)(W + (size_t)(k0 + w_kr0)     * N + colBase + w_nc0 * 4);
        rw1 = *(const float4*)(W + (size_t)(k0 + w_kr0 + 8) * N + colBase + w_nc0 * 4);
    };

    auto sts = [&](int st) {
        uint32_t* Ahp = sm + st * STAGE;
        uint32_t* Whp = Ahp + 2048;
        uint32_t* Alp = Ahp + 4096;
        uint32_t* Wlp = Ahp + 6144;
        // A: element k -> pl=k&3 (=e), ix=k>>2 with pair swizzle
        {
            const int jp = a_ix0 >> 1, wbit = a_ix0 & 1;
            float va0[4] = {ra0.x, ra0.y, ra0.z, ra0.w};
            float va1[4] = {ra1.x, ra1.y, ra1.z, ra1.w};
#pragma unroll
            for (int e = 0; e < 4; e++) {
                int ixs = ((jp ^ (e & 1)) << 1) | wbit;
                uint32_t h0 = f2tf32(va0[e]);
                uint32_t h1 = f2tf32(va1[e]);
                Ahp[e * 512 + a_r0 * 4 + ixs]        = h0;
                Ahp[e * 512 + (a_r0 + 64) * 4 + ixs] = h1;
                if (SPLIT) {
                    Alp[e * 512 + a_r0 * 4 + ixs]        = f2tf32(va0[e] - __uint_as_float(h0));
                    Alp[e * 512 + (a_r0 + 64) * 4 + ixs] = f2tf32(va1[e] - __uint_as_float(h1));
                }
            }
        }
        // W: element (k=kr, n) -> pl=kr&3, ix=kr>>2 with pair swizzle
#pragma unroll
        for (int half = 0; half < 2; half++) {
            int kr = w_kr0 + half * 8;
            float4 v = half ? rw1 : rw0;
            float vv[4] = {v.x, v.y, v.z, v.w};
            int pl = kr & 3, ix = kr >> 2;
            int ixs = (((ix >> 1) ^ (pl & 1)) << 1) | (ix & 1);
#pragma unroll
            for (int e = 0; e < 4; e++) {
                uint32_t h = f2tf32(vv[e]);
                Whp[pl * 512 + (w_nc0 * 4 + e) * 4 + ixs] = h;
                if (SPLIT) Wlp[pl * 512 + (w_nc0 * 4 + e) * 4 + ixs] =
                    f2tf32(vv[e] - __uint_as_float(h));
            }
        }
    };

    auto compute = [&](int st) {
        const uint32_t* Ahp = sm + st * STAGE;
        const uint32_t* Whp = Ahp + 2048;
        const uint32_t* Alp = Ahp + 4096;
        const uint32_t* Wlp = Ahp + 6144;
#pragma unroll
        for (int j = 0; j < 2; j++) {
            const int ja = 2 * (j ^ (tig & 1));
            uint32_t ah[4][4], al[4][4];
#pragma unroll
            for (int mt = 0; mt < 4; mt++) {
                int rl = wm + mt * 16 + g, rh = rl + 8;
                uint2 h0 = *(const uint2*)&Ahp[tig * 512 + rl * 4 + ja];
                uint2 h1 = *(const uint2*)&Ahp[tig * 512 + rh * 4 + ja];
                ah[mt][0] = h0.x; ah[mt][2] = h0.y;
                ah[mt][1] = h1.x; ah[mt][3] = h1.y;
                if (SPLIT) {
                    uint2 l0 = *(const uint2*)&Alp[tig * 512 + rl * 4 + ja];
                    uint2 l1 = *(const uint2*)&Alp[tig * 512 + rh * 4 + ja];
                    al[mt][0] = l0.x; al[mt][2] = l0.y;
                    al[mt][1] = l1.x; al[mt][3] = l1.y;
                }
            }
#pragma unroll
            for (int nt = 0; nt < 4; nt++) {
                int cn = wn + nt * 8 + g;
                uint2 bh = *(const uint2*)&Whp[tig * 512 + cn * 4 + ja];
#pragma unroll
                for (int mt = 0; mt < 4; mt++)
                    mma_tf32(acc[mt][nt][0], acc[mt][nt][1], acc[mt][nt][2], acc[mt][nt][3],
                             ah[mt][0], ah[mt][1], ah[mt][2], ah[mt][3], bh.x, bh.y);
                if (SPLIT) {
                    uint2 bl = *(const uint2*)&Wlp[tig * 512 + cn * 4 + ja];
#pragma unroll
                    for (int mt = 0; mt < 4; mt++) {
                        mma_tf32(acc[mt][nt][0], acc[mt][nt][1], acc[mt][nt][2], acc[mt][nt][3],
                                 ah[mt][0], ah[mt][1], ah[mt][2], ah[mt][3], bl.x, bl.y);
                        mma_tf32(acc[mt][nt][0], acc[mt][nt][1], acc[mt][nt][2], acc[mt][nt][3],
                                 al[mt][0], al[mt][1], al[mt][2], al[mt][3], bh.x, bh.y);
                    }
                }
            }
        }
    };

    // ---- software pipeline: prefetch next tile during compute ----
    ldg(0);
    sts(0);
    __syncthreads();
    int st = 0;
    for (int k0 = 0; k0 < K; k0 += BK) {
        const bool has_next = (k0 + BK < K);
        if (has_next) ldg(k0 + BK);      // LDGs in flight over compute
        compute(st);
        if (has_next) {
            sts(st ^ 1);
            __syncthreads();
            st ^= 1;
        }
    }

    // --- Epilogue: optional RoPE on adjacent (even,odd) column pairs ---
#pragma unroll
    for (int mt = 0; mt < 4; mt++) {
        int rowlo = rowBase + wm + mt * 16 + g;
        int rowhi = rowlo + 8;
#pragma unroll
        for (int nt = 0; nt < 4; nt++) {
            int gc = colBase + wn + nt * 8 + 2 * tig;
            float e0 = acc[mt][nt][0], o0 = acc[mt][nt][1];
            float e1 = acc[mt][nt][2], o1 = acc[mt][nt][3];
            if (DO_ROPE) {
                int i0 = (gc & (CC - 1)) >> 1;
                int tlo = rowlo & (TT - 1), thi = rowhi & (TT - 1);
                float cl = cosT[tlo * HALF + i0], sl = sinT[tlo * HALF + i0];
                float ch = cosT[thi * HALF + i0], sh = sinT[thi * HALF + i0];
                float r0 = e0 * cl - o0 * sl, r1 = e0 * sl + o0 * cl;
                float r2 = e1 * ch - o1 * sh, r3 = e1 * sh + o1 * ch;
                e0 = r0; o0 = r1; e1 = r2; o1 = r3;
            }
            *(float2*)(Out + (size_t)rowlo * N + gc) = make_float2(e0 * scale, o0 * scale);
            *(float2*)(Out + (size_t)rowhi * N + gc) = make_float2(e1 * scale, o1 * scale);
        }
    }
}

// ---------------------------------------------------------------------------
// Fused routed attention: R1 structure, dots + accumulation in packed f32x2.
// ---------------------------------------------------------------------------
__global__ void __launch_bounds__(256) attn_kernel(
    const float* __restrict__ Q, const float* __restrict__ K,
    const float* __restrict__ V, float* __restrict__ Y)
{
    constexpr int SBLK = 16;
    __shared__ float4 ks[SBLK][CC / 4];   // 32KB

    const int tid  = threadIdx.x;
    const int w    = tid >> 5;
    const int lane = tid & 31;
    const int r    = blockIdx.x * 8 + w;
    const int t    = r & (TT - 1);
    const int tmax = (blockIdx.x * 8 + 7) & (TT - 1);

    ull q2[NB][8];
    {
        const float4* qp4 = (const float4*)(Q + (size_t)r * QN);
#pragma unroll
        for (int n = 0; n < NB; n++)
#pragma unroll
            for (int jj = 0; jj < 4; jj++) {
                float4 v = qp4[n * 128 + jj * 32 + lane];
                ulonglong2 u = *(ulonglong2*)&v;
                q2[n][jj * 2]     = u.x;
                q2[n][jj * 2 + 1] = u.y;
            }
    }

    ull acc2[8];
#pragma unroll
    for (int i = 0; i < 8; i++) acc2[i] = 0ull;
    float m = -1e30f, l = 0.f;

    const float* kb = K + (size_t)(r - t) * CC;
    const float* vb = V + (size_t)(r - t) * QN;

    for (int s0 = 0; s0 <= tmax; s0 += SBLK) {
#pragma unroll
        for (int i = 0; i < 8; i++) {
            int slot = tid + i * 256;
            int si = slot >> 7, cj = slot & 127;
            ks[si][cj] = *(const float4*)(kb + (size_t)(s0 + si) * CC + cj * 4);
        }
        __syncthreads();

        int send = t - s0; if (send > SBLK - 1) send = SBLK - 1;
        for (int si = 0; si <= send; si++) {
            ull dd[NB] = {0ull, 0ull, 0ull, 0ull};
#pragma unroll
            for (int jj = 0; jj < 4; jj++) {
                float4 kv = ks[si][jj * 32 + lane];
                ulonglong2 ku = *(ulonglong2*)&kv;
#pragma unroll
                for (int n = 0; n < NB; n++) {
                    ffma2(dd[n], q2[n][jj * 2],     ku.x);
                    ffma2(dd[n], q2[n][jj * 2 + 1], ku.y);
                }
            }
            float d[NB];
#pragma unroll
            for (int n = 0; n < NB; n++) {
                float2 f = unpk(dd[n]);
                d[n] = f.x + f.y;
            }
#pragma unroll
            for (int off = 16; off > 0; off >>= 1) {
#pragma unroll
                for (int n = 0; n < NB; n++)
                    d[n] += __shfl_xor_sync(0xffffffffu, d[n], off);
            }

            float smax = d[0]; int nsel = 0;
            if (d[1] > smax) { smax = d[1]; nsel = 1; }
            if (d[2] > smax) { smax = d[2]; nsel = 2; }
            if (d[3] > smax) { smax = d[3]; nsel = 3; }

            float mnew  = fmaxf(m, smax);
            float alpha = __expf(m - mnew);
            float p     = __expf(smax - mnew);
            l = l * alpha + p;
            m = mnew;

            ull alpha2 = pack2(alpha, alpha);
            ull p2     = pack2(p, p);
            const float4* vr = (const float4*)(vb + (size_t)(s0 + si) * QN + (size_t)nsel * CC);
#pragma unroll
            for (int jj = 0; jj < 4; jj++) {
                float4 vv = vr[jj * 32 + lane];
                ulonglong2 vu = *(ulonglong2*)&vv;
                acc2[jj * 2]     = fmul2(acc2[jj * 2],     alpha2);
                acc2[jj * 2 + 1] = fmul2(acc2[jj * 2 + 1], alpha2);
                ffma2(acc2[jj * 2],     vu.x, p2);
                ffma2(acc2[jj * 2 + 1], vu.y, p2);
            }
        }
        __syncthreads();
    }

    float inv = 1.f / l;
    float* yp = Y + (size_t)r * CC;
#pragma unroll
    for (int jj = 0; jj < 4; jj++) {
        float2 a0 = unpk(acc2[jj * 2]);
        float2 a1 = unpk(acc2[jj * 2 + 1]);
        *(float4*)(yp + jj * 128 + lane * 4) =
            make_float4(a0.x * inv, a0.y * inv, a1.x * inv, a1.y * inv);
    }
}

// ---------------------------------------------------------------------------
extern "C" void kernel_launch(void* const* d_in, const int* in_sizes, int n_in,
                              void* d_out, int out_size)
{
    const float* a    = (const float*)d_in[0];
    const float* x    = (const float*)d_in[1];
    const float* Wq   = (const float*)d_in[2];
    const float* Wk   = (const float*)d_in[3];
    const float* Wv   = (const float*)d_in[4];
    const float* Wo   = (const float*)d_in[5];
    const float* cosT = (const float*)d_in[6];
    const float* sinT = (const float*)d_in[7];
    float* out = (float*)d_out;

    float* Qb; cudaGetSymbolAddress((void**)&Qb, g_Q);
    float* Kb; cudaGetSymbolAddress((void**)&Kb, g_K);
    float* Vb; cudaGetSymbolAddress((void**)&Vb, g_V);
    float* Yb; cudaGetSymbolAddress((void**)&Yb, g_Y);

    const int M = BB * TT;
    const float qscale = 0.04419417382415922f;  // 1/sqrt(512)

    const size_t smem_split = 2 * 8192 * sizeof(uint32_t);   // 64KB
    const size_t smem_plain = 2 * 4096 * sizeof(uint32_t);   // 32KB
    cudaFuncSetAttribute((void*)gemm_tc<1,1>,
                         cudaFuncAttributeMaxDynamicSharedMemorySize, (int)smem_split);

    dim3 thr(256);
    // Q,K feed routing argmax -> split-tf32 (fp32-accurate)
    gemm_tc<1,1><<<dim3(QN / 128, M / 128), thr, smem_split>>>(a, Wq, Qb, M, QN, CC, cosT, sinT, qscale);
    gemm_tc<1,1><<<dim3(CC / 128, M / 128), thr, smem_split>>>(x, Wk, Kb, M, CC, CC, cosT, sinT, 1.0f);
    // V, Wo linear in output -> plain tf32
    gemm_tc<0,0><<<dim3(QN / 128, M / 128), thr, smem_plain>>>(a, Wv, Vb, M, QN, CC, nullptr, nullptr, 1.0f);
    attn_kernel<<<M / 8, thr>>>(Qb, Kb, Vb, Yb);
    gemm_tc<0,0><<<dim3(CC / 128, M / 128), thr, smem_plain>>>(Yb, Wo, out, M, CC, CC, nullptr, nullptr, 1.0f);
}